// round 12
// baseline (speedup 1.0000x reference)
#include <cuda_runtime.h>
#include <math.h>

#define TT   512
#define BB   64
#define HH   512
#define GG   2048   // 4*HH
#define EE   512
#define NCTA 128

typedef unsigned long long u64;

// ---------------- packed fp32x2 helpers (sm_103a FFMA2) ----------------
__device__ __forceinline__ u64 pack2(float lo, float hi) {
    u64 r; asm("mov.b64 %0,{%1,%2};" : "=l"(r) : "f"(lo), "f"(hi)); return r;
}
__device__ __forceinline__ void ffma2(u64 &d, u64 a, u64 b) {
    asm("fma.rn.f32x2 %0,%1,%2,%0;" : "+l"(d) : "l"(a), "l"(b));
}
__device__ __forceinline__ u64 fadd2(u64 a, u64 b) {
    u64 r; asm("add.rn.f32x2 %0,%1,%2;" : "=l"(r) : "l"(a), "l"(b)); return r;
}
__device__ __forceinline__ float2 unpack2(u64 v) {
    float2 f; asm("mov.b64 {%0,%1},%2;" : "=f"(f.x), "=f"(f.y) : "l"(v)); return f;
}
// fast activations (MUFU-based, ~1e-7 rel err, correct saturation)
__device__ __forceinline__ float fast_sig(float x)  { return 1.f / (1.f + __expf(-x)); }
__device__ __forceinline__ float fast_tanh(float x) { float e = __expf(2.f * x); return 1.f - 2.f / (e + 1.f); }

// ---------------- scratch (device globals) ----------------
__device__ float g_x0[(size_t)TT * EE * BB];     // embedded input,  [T][E][B]
__device__ float g_xw[(size_t)TT * GG * BB];     // x@Wih0 + bias0,  [T][G][B]
__device__ float g_y1[(size_t)TT * HH * BB];     // layer1 outputs,  [T][H][B]
__device__ float g_hall[2 * 1024 * BB];          // [2 buf][h0:0-511 | h1:512-1023][B]
__device__ unsigned g_bar;                       // grid barrier counter

// ---------------- grid barrier (128 co-resident CTAs, wrap-safe) ----------------
__device__ __forceinline__ void grid_sync() {
    __syncthreads();
    if (threadIdx.x == 0) {
        __threadfence();
        unsigned ticket = atomicAdd(&g_bar, 1u);
        unsigned target = ticket - (ticket & (NCTA - 1)) + NCTA;
        while ((int)(*(volatile unsigned*)&g_bar - target) < 0) { }
        __threadfence();
    }
    __syncthreads();
}

// ---------------- embedding gather ----------------
__global__ void embed_kernel(const int* __restrict__ src,
                             const float* __restrict__ emb) {
    size_t idx = (size_t)blockIdx.x * blockDim.x + threadIdx.x;
    if (idx >= (size_t)TT * EE * BB) return;
    int b = (int)(idx & 63);
    int e = (int)((idx >> 6) & (EE - 1));
    int t = (int)(idx >> 15);
    g_x0[idx] = emb[(size_t)src[t * BB + b] * EE + e];
}

// ---------------- GEMM v2: C[t][col][b] = sum_k A[t][k][b]*W[col][k] + bias ----------------
// CTA 256 thr = 8 warps; CTA tile 128 cols x 64 b. Warp: 16 cols (8 colpairs) x 64 b.
// Lane = batch pair; A via LDG.64 (coalesced, L1-served across warps); W staged per
// 128-k chunk as natural float2 colpairs -> 4 uniform LDS.128/kk. 64 KB smem, 3 CTA/SM.
__global__ void __launch_bounds__(256) gemm_xw_kernel(const float* __restrict__ W,
                                                      const float* __restrict__ b1,
                                                      const float* __restrict__ b2) {
    const float* __restrict__ A = g_x0;
    float* __restrict__ C = g_xw;

    extern __shared__ float2 sW[];   // [128 kk][64 colpairs] (64 KB)

    const int tid  = threadIdx.x;
    const int t    = blockIdx.y;
    const int n0   = blockIdx.x * 128;
    const int wid  = tid >> 5;
    const int lane = tid & 31;
    const int cp0  = wid * 8;        // 8 colpairs per warp
    const int f_cp = tid & 63;       // fill: colpair
    const int f_kg = tid >> 6;       // fill: k group (32 k each)

    u64 acc0[8], acc1[8];
    #pragma unroll
    for (int i = 0; i < 8; ++i) { acc0[i] = 0ull; acc1[i] = 0ull; }

    for (int kc = 0; kc < 512; kc += 128) {
        __syncthreads();
        // fill W chunk: sW[kk][cp] = (W[n0+2cp][kc+kk], W[n0+2cp+1][kc+kk])
        {
            const float* we = W + (size_t)(n0 + 2 * f_cp) * 512 + kc + f_kg * 32;
            const float* wo = we + 512;
            #pragma unroll
            for (int i = 0; i < 8; ++i) {
                float4 e = *(const float4*)(we + i * 4);
                float4 o = *(const float4*)(wo + i * 4);
                int k = f_kg * 32 + i * 4;
                sW[(k + 0) * 64 + f_cp] = make_float2(e.x, o.x);
                sW[(k + 1) * 64 + f_cp] = make_float2(e.y, o.y);
                sW[(k + 2) * 64 + f_cp] = make_float2(e.z, o.z);
                sW[(k + 3) * 64 + f_cp] = make_float2(e.w, o.w);
            }
        }
        __syncthreads();

        const u64* ap = (const u64*)(A + ((size_t)t * 512 + kc) * 64) + lane;
        #pragma unroll 8
        for (int kk = 0; kk < 128; ++kk) {
            float2 av = unpack2(ap[(size_t)kk * 32]);
            u64 d0 = pack2(av.x, av.x);
            u64 d1 = pack2(av.y, av.y);
            const ulonglong2* wk = (const ulonglong2*)(sW + kk * 64 + cp0);
            #pragma unroll
            for (int p = 0; p < 4; ++p) {
                ulonglong2 w2 = wk[p];
                ffma2(acc0[2 * p + 0], w2.x, d0); ffma2(acc1[2 * p + 0], w2.x, d1);
                ffma2(acc0[2 * p + 1], w2.y, d0); ffma2(acc1[2 * p + 1], w2.y, d1);
            }
        }
    }

    #pragma unroll
    for (int i = 0; i < 8; ++i) {
        int cp  = cp0 + i;
        int col = n0 + 2 * cp;
        float2 x1 = ((const float2*)b1)[(n0 >> 1) + cp];
        float2 x2 = ((const float2*)b2)[(n0 >> 1) + cp];
        u64 bia = pack2(x1.x + x2.x, x1.y + x2.y);
        float2 f0 = unpack2(fadd2(acc0[i], bia));
        float2 f1 = unpack2(fadd2(acc1[i], bia));
        size_t base = ((size_t)t * GG + col) * BB + 2 * lane;
        *(u64*)(C + base)      = pack2(f0.x, f1.x);   // col even, batches 2l, 2l+1
        *(u64*)(C + base + BB) = pack2(f0.y, f1.y);   // col odd
    }
}

// ---------------- fused 2-layer persistent LSTM recurrence ----------------
// Step s: layer0 @ t=s and layer1 @ t=s-1. One pass over h0 feeds BOTH Whh0 and Wih1.
__global__ void __launch_bounds__(256, 1) lstm_fused_kernel(
        const float* __restrict__ Whh0,
        const float* __restrict__ Wih1,
        const float* __restrict__ Whh1,
        const float* __restrict__ bih1,
        const float* __restrict__ bhh1) {
    extern __shared__ float smem[];
    float2* sWp0 = (float2*)smem;                 // [512 k][8 rp]  Whh0 (32 KB)
    float2* sWp1 = sWp0 + 512 * 8;                // [1024 k][8 rp] Wih1|Whh1 (64 KB)
    u64*    sPA  = (u64*)(sWp1 + 1024 * 8);       // [8 ks][8 rp][64 b] (32 KB)
    u64*    sPB  = sPA + 8 * 8 * 64;              // same (32 KB)
    float*  sC0  = (float*)(sPB + 8 * 8 * 64);    // [4][64]
    float*  sC1  = sC0 + 256;                     // [4][64]
    float*  sB1  = sC1 + 256;                     // [16]

    const int tid = threadIdx.x;
    const int cta = blockIdx.x;
    const int u0  = cta * 4;

    // ---- weight fills: sWp[k][rp] = (W[row_e][k], W[row_o][k]), rp = q*2+jh ----
    {
        const int rp = tid >> 5;              // 0..7
        const int ln = tid & 31;
        const int q = rp >> 1, jh = rp & 1;
        const int re = q * 512 + u0 + 2 * jh;
        const float* we0 = Whh0 + (size_t)re * 512;
        const float* wo0 = we0 + 512;
        const float* we1 = Wih1 + (size_t)re * 512;
        const float* wo1 = we1 + 512;
        const float* we2 = Whh1 + (size_t)re * 512;
        const float* wo2 = we2 + 512;
        #pragma unroll
        for (int i = 0; i < 4; ++i) {
            int k = ln * 16 + i * 4;
            float4 ae = *(const float4*)(we0 + k);
            float4 ao = *(const float4*)(wo0 + k);
            sWp0[(k + 0) * 8 + rp] = make_float2(ae.x, ao.x);
            sWp0[(k + 1) * 8 + rp] = make_float2(ae.y, ao.y);
            sWp0[(k + 2) * 8 + rp] = make_float2(ae.z, ao.z);
            sWp0[(k + 3) * 8 + rp] = make_float2(ae.w, ao.w);
            float4 be = *(const float4*)(we1 + k);
            float4 bo = *(const float4*)(wo1 + k);
            sWp1[(k + 0) * 8 + rp] = make_float2(be.x, bo.x);
            sWp1[(k + 1) * 8 + rp] = make_float2(be.y, bo.y);
            sWp1[(k + 2) * 8 + rp] = make_float2(be.z, bo.z);
            sWp1[(k + 3) * 8 + rp] = make_float2(be.w, bo.w);
            float4 ce = *(const float4*)(we2 + k);
            float4 co = *(const float4*)(wo2 + k);
            sWp1[(512 + k + 0) * 8 + rp] = make_float2(ce.x, co.x);
            sWp1[(512 + k + 1) * 8 + rp] = make_float2(ce.y, co.y);
            sWp1[(512 + k + 2) * 8 + rp] = make_float2(ce.z, co.z);
            sWp1[(512 + k + 3) * 8 + rp] = make_float2(ce.w, co.w);
        }
    }
    // ---- init ----
    {
        #pragma unroll
        for (int i = 0; i < 4; ++i) {
            int e   = tid + i * 256;
            int buf = e >> 9;
            int rem = e & 511;
            int r8  = rem >> 6;
            int b   = rem & 63;
            int grow = (r8 < 4) ? (u0 + r8) : (512 + u0 + (r8 - 4));
            g_hall[((size_t)buf * 1024 + grow) * 64 + b] = 0.f;
        }
        sC0[tid] = 0.f;
        sC1[tid] = 0.f;
        if (tid < 16) {
            int q = tid >> 2, j = tid & 3;
            int col = q * 512 + u0 + j;
            sB1[tid] = bih1[col] + bhh1[col];
        }
    }
    grid_sync();

    const int ks = tid >> 5;                // warp = k-slice
    const int bp = tid & 31;                // batch pair (batches 2bp, 2bp+1)
    const int jj = tid >> 6, bb = tid & 63; // gate-phase mapping

    int cur = 0;
    for (int s = 0; s <= TT; ++s) {
        const bool doA = (s < TT);
        const bool doB = (s >= 1);
        const int  sx  = doA ? s : (TT - 1);   // clamped (values unused when !doA)

        float xv[4];
        #pragma unroll
        for (int q = 0; q < 4; ++q)
            xv[q] = __ldg(g_xw + ((size_t)sx * GG + q * 512 + u0 + jj) * 64 + bb);

        // ---- pass 1 over h0[cur]: feeds accA (Whh0) and accB (Wih1) ----
        u64 aA0[8], aA1[8], aB0[8], aB1[8];
        #pragma unroll
        for (int i = 0; i < 8; ++i) { aA0[i] = 0ull; aA1[i] = 0ull; aB0[i] = 0ull; aB1[i] = 0ull; }
        {
            const u64* hp = (const u64*)(g_hall + ((size_t)cur * 1024 + ks * 64) * 64) + bp;
            const ulonglong2* wq0 = (const ulonglong2*)(sWp0 + (ks * 64) * 8);
            const ulonglong2* wq1 = (const ulonglong2*)(sWp1 + (ks * 64) * 8);
            #pragma unroll 8
            for (int kk = 0; kk < 64; ++kk) {
                u64 hraw = __ldcg(hp + (size_t)kk * 32);
                float2 hv = unpack2(hraw);
                u64 hd0 = pack2(hv.x, hv.x);
                u64 hd1 = pack2(hv.y, hv.y);
                const ulonglong2* wk0 = wq0 + kk * 4;
                const ulonglong2* wk1 = wq1 + kk * 4;
                #pragma unroll
                for (int p = 0; p < 4; ++p) {
                    ulonglong2 w2 = wk0[p];
                    ffma2(aA0[2 * p + 0], w2.x, hd0); ffma2(aA1[2 * p + 0], w2.x, hd1);
                    ffma2(aA0[2 * p + 1], w2.y, hd0); ffma2(aA1[2 * p + 1], w2.y, hd1);
                    ulonglong2 v2 = wk1[p];
                    ffma2(aB0[2 * p + 0], v2.x, hd0); ffma2(aB1[2 * p + 0], v2.x, hd1);
                    ffma2(aB0[2 * p + 1], v2.y, hd0); ffma2(aB1[2 * p + 1], v2.y, hd1);
                }
            }
        }
        // ---- pass 2 over h1[cur]: accB += Whh1 ----
        {
            const u64* hp = (const u64*)(g_hall + ((size_t)cur * 1024 + 512 + ks * 64) * 64) + bp;
            const ulonglong2* wq2 = (const ulonglong2*)(sWp1 + (512 + ks * 64) * 8);
            #pragma unroll 8
            for (int kk = 0; kk < 64; ++kk) {
                u64 hraw = __ldcg(hp + (size_t)kk * 32);
                float2 hv = unpack2(hraw);
                u64 hd0 = pack2(hv.x, hv.x);
                u64 hd1 = pack2(hv.y, hv.y);
                const ulonglong2* wk = wq2 + kk * 4;
                #pragma unroll
                for (int p = 0; p < 4; ++p) {
                    ulonglong2 w2 = wk[p];
                    ffma2(aB0[2 * p + 0], w2.x, hd0); ffma2(aB1[2 * p + 0], w2.x, hd1);
                    ffma2(aB0[2 * p + 1], w2.y, hd0); ffma2(aB1[2 * p + 1], w2.y, hd1);
                }
            }
        }
        #pragma unroll
        for (int rp = 0; rp < 8; ++rp) {
            *(ulonglong2*)(sPA + ((ks * 8 + rp) * 64 + 2 * bp)) = make_ulonglong2(aA0[rp], aA1[rp]);
            *(ulonglong2*)(sPB + ((ks * 8 + rp) * 64 + 2 * bp)) = make_ulonglong2(aB0[rp], aB1[rp]);
        }
        __syncthreads();

        // ---- gates A: layer0 @ t=s ----
        if (doA) {
            float g4[4];
            #pragma unroll
            for (int q = 0; q < 4; ++q) {
                int rp = q * 2 + (jj >> 1);
                int rh = jj & 1;
                u64 sum = sPA[(0 * 8 + rp) * 64 + bb];
                #pragma unroll
                for (int k2 = 1; k2 < 8; ++k2)
                    sum = fadd2(sum, sPA[(k2 * 8 + rp) * 64 + bb]);
                float2 sv = unpack2(sum);
                g4[q] = xv[q] + (rh ? sv.y : sv.x);
            }
            float iv = fast_sig(g4[0]);
            float fv = fast_sig(g4[1]);
            float gv = fast_tanh(g4[2]);
            float ov = fast_sig(g4[3]);
            float c = fv * sC0[jj * 64 + bb] + iv * gv;
            sC0[jj * 64 + bb] = c;
            float h = ov * fast_tanh(c);
            g_hall[((size_t)(cur ^ 1) * 1024 + u0 + jj) * 64 + bb] = h;
        }
        // ---- gates B: layer1 @ t=s-1 ----
        if (doB) {
            float g4[4];
            #pragma unroll
            for (int q = 0; q < 4; ++q) {
                int rp = q * 2 + (jj >> 1);
                int rh = jj & 1;
                u64 sum = sPB[(0 * 8 + rp) * 64 + bb];
                #pragma unroll
                for (int k2 = 1; k2 < 8; ++k2)
                    sum = fadd2(sum, sPB[(k2 * 8 + rp) * 64 + bb]);
                float2 sv = unpack2(sum);
                g4[q] = sB1[q * 4 + jj] + (rh ? sv.y : sv.x);
            }
            float iv = fast_sig(g4[0]);
            float fv = fast_sig(g4[1]);
            float gv = fast_tanh(g4[2]);
            float ov = fast_sig(g4[3]);
            float c = fv * sC1[jj * 64 + bb] + iv * gv;
            sC1[jj * 64 + bb] = c;
            float h = ov * fast_tanh(c);
            g_hall[((size_t)(cur ^ 1) * 1024 + 512 + u0 + jj) * 64 + bb] = h;
            g_y1[((size_t)(s - 1) * HH + u0 + jj) * 64 + bb] = h;
        }
        grid_sync();
        cur ^= 1;
    }
}

// ---------------- output gather ----------------
__global__ void out_kernel(const int* __restrict__ sen_len, float* __restrict__ out) {
    int idx = blockIdx.x * blockDim.x + threadIdx.x;
    if (idx >= BB * HH) return;
    int b = idx >> 9;
    int u = idx & (HH - 1);
    int t = sen_len[b] - 1;
    out[idx] = g_y1[((size_t)t * HH + u) * BB + b];
}

// ---------------- launch ----------------
static const int GEMM_SMEM = 128 * 64 * (int)sizeof(float2);   // 65536
static const int REC_SMEM  = (512 * 8 + 1024 * 8) * 8          // sWp0 + sWp1 (float2)
                           + 2 * (8 * 8 * 64) * 8              // sPA + sPB (u64)
                           + 2 * 256 * 4 + 16 * 4;             // sC0,sC1,sB1  = 165952

extern "C" void kernel_launch(void* const* d_in, const int* in_sizes, int n_in,
                              void* d_out, int out_size) {
    const int*   src     = (const int*)d_in[0];
    const int*   sen_len = (const int*)d_in[1];
    const float* emb     = (const float*)d_in[2];
    const float* Wih0    = (const float*)d_in[3];
    const float* Whh0    = (const float*)d_in[4];
    const float* bih0    = (const float*)d_in[5];
    const float* bhh0    = (const float*)d_in[6];
    const float* Wih1    = (const float*)d_in[7];
    const float* Whh1    = (const float*)d_in[8];
    const float* bih1    = (const float*)d_in[9];
    const float* bhh1    = (const float*)d_in[10];
    float* out = (float*)d_out;

    cudaFuncSetAttribute(gemm_xw_kernel,
                         cudaFuncAttributeMaxDynamicSharedMemorySize, GEMM_SMEM);
    cudaFuncSetAttribute(lstm_fused_kernel,
                         cudaFuncAttributeMaxDynamicSharedMemorySize, REC_SMEM);

    embed_kernel<<<(TT * EE * BB + 255) / 256, 256>>>(src, emb);

    dim3 ggrid(GG / 128, TT);
    gemm_xw_kernel<<<ggrid, 256, GEMM_SMEM>>>(Wih0, bih0, bhh0);

    lstm_fused_kernel<<<NCTA, 256, REC_SMEM>>>(Whh0, Wih1, Whh1, bih1, bhh1);

    out_kernel<<<(BB * HH + 255) / 256, 256>>>(sen_len, out);
}

// round 13
// speedup vs baseline: 1.0353x; 1.0353x over previous
#include <cuda_runtime.h>
#include <math.h>

#define TT   512
#define BB   64
#define HH   512
#define GG   2048   // 4*HH
#define EE   512
#define NCTA 128

typedef unsigned long long u64;

// ---------------- packed fp32x2 helpers (sm_103a FFMA2) ----------------
__device__ __forceinline__ u64 pack2(float lo, float hi) {
    u64 r; asm("mov.b64 %0,{%1,%2};" : "=l"(r) : "f"(lo), "f"(hi)); return r;
}
__device__ __forceinline__ void ffma2(u64 &d, u64 a, u64 b) {
    asm("fma.rn.f32x2 %0,%1,%2,%0;" : "+l"(d) : "l"(a), "l"(b));
}
__device__ __forceinline__ u64 fadd2(u64 a, u64 b) {
    u64 r; asm("add.rn.f32x2 %0,%1,%2;" : "=l"(r) : "l"(a), "l"(b)); return r;
}
__device__ __forceinline__ float2 unpack2(u64 v) {
    float2 f; asm("mov.b64 {%0,%1},%2;" : "=f"(f.x), "=f"(f.y) : "l"(v)); return f;
}
// fast activations (MUFU-based, ~1e-7 rel err, correct saturation)
__device__ __forceinline__ float fast_sig(float x)  { return 1.f / (1.f + __expf(-x)); }
__device__ __forceinline__ float fast_tanh(float x) { float e = __expf(2.f * x); return 1.f - 2.f / (e + 1.f); }

// ---------------- scratch (device globals) ----------------
__device__ float g_x0[(size_t)TT * EE * BB];     // embedded input,  [T][E][B]
__device__ float g_xw[(size_t)TT * GG * BB];     // x@Wih0 + bias0,  [T][G][B]
__device__ float g_y1[(size_t)TT * HH * BB];     // layer1 outputs,  [T][H][B]
__device__ float g_hall[2 * 1024 * BB];          // [2 buf][h0:0-511 | h1:512-1023][B]
__device__ unsigned g_bar;                       // grid barrier counter

// ---------------- grid barrier (128 co-resident CTAs, wrap-safe) ----------------
__device__ __forceinline__ void grid_sync() {
    __syncthreads();
    if (threadIdx.x == 0) {
        __threadfence();
        unsigned ticket = atomicAdd(&g_bar, 1u);
        unsigned target = ticket - (ticket & (NCTA - 1)) + NCTA;
        while ((int)(*(volatile unsigned*)&g_bar - target) < 0) { }
        __threadfence();
    }
    __syncthreads();
}

// ---------------- embedding gather ----------------
__global__ void embed_kernel(const int* __restrict__ src,
                             const float* __restrict__ emb) {
    size_t idx = (size_t)blockIdx.x * blockDim.x + threadIdx.x;
    if (idx >= (size_t)TT * EE * BB) return;
    int b = (int)(idx & 63);
    int e = (int)((idx >> 6) & (EE - 1));
    int t = (int)(idx >> 15);
    g_x0[idx] = emb[(size_t)src[t * BB + b] * EE + e];
}

// ---------------- GEMM (R3 version, measured 1.47ms): layer-0 xW only ----------------
__global__ void __launch_bounds__(128) gemm_xw_kernel(const float* __restrict__ W,
                                                      const float* __restrict__ b1,
                                                      const float* __restrict__ b2) {
    const float* __restrict__ A = g_x0;
    float* __restrict__ C = g_xw;

    __shared__ float As[16][64];     // [k][b]
    __shared__ float Ws[16][132];    // [k][col], padded

    const int tid = threadIdx.x;
    const int t   = blockIdx.y;
    const int n0  = blockIdx.x * 128;
    const int bx  = tid & 7;
    const int cy  = tid >> 3;
    const int b0  = bx * 8;
    const int c0  = cy * 8;
    const int lw_c = tid >> 2;
    const int lw_q = tid & 3;

    u64 acc[8][4];
    #pragma unroll
    for (int j = 0; j < 8; ++j)
        #pragma unroll
        for (int p = 0; p < 4; ++p) acc[j][p] = 0ull;

    for (int k0 = 0; k0 < 512; k0 += 16) {
        #pragma unroll
        for (int u = 0; u < 2; ++u) {
            int f  = tid * 2 + u;
            int kk = f >> 4, bb4 = (f & 15) * 4;
            *(float4*)&As[kk][bb4] =
                *(const float4*)(A + ((size_t)t * 512 + k0 + kk) * 64 + bb4);
        }
        #pragma unroll
        for (int cb = 0; cb < 4; ++cb) {
            int c = cb * 32 + lw_c;
            float4 w = *(const float4*)(W + (size_t)(n0 + c) * 512 + k0 + lw_q * 4);
            Ws[lw_q * 4 + 0][c] = w.x;
            Ws[lw_q * 4 + 1][c] = w.y;
            Ws[lw_q * 4 + 2][c] = w.z;
            Ws[lw_q * 4 + 3][c] = w.w;
        }
        __syncthreads();

        #pragma unroll
        for (int kk = 0; kk < 16; ++kk) {
            ulonglong2 a01 = *(const ulonglong2*)&As[kk][b0];
            ulonglong2 a23 = *(const ulonglong2*)&As[kk][b0 + 4];
            float4 wA = *(const float4*)&Ws[kk][c0];
            float4 wB = *(const float4*)&Ws[kk][c0 + 4];
            float wv[8] = {wA.x, wA.y, wA.z, wA.w, wB.x, wB.y, wB.z, wB.w};
            #pragma unroll
            for (int j = 0; j < 8; ++j) {
                u64 wp = pack2(wv[j], wv[j]);
                ffma2(acc[j][0], a01.x, wp);
                ffma2(acc[j][1], a01.y, wp);
                ffma2(acc[j][2], a23.x, wp);
                ffma2(acc[j][3], a23.y, wp);
            }
        }
        __syncthreads();
    }

    #pragma unroll
    for (int j = 0; j < 8; ++j) {
        int col = n0 + c0 + j;
        float bias = b1[col] + b2[col];
        float2 p0 = unpack2(acc[j][0]);
        float2 p1 = unpack2(acc[j][1]);
        float2 p2 = unpack2(acc[j][2]);
        float2 p3 = unpack2(acc[j][3]);
        float4 v0 = make_float4(p0.x + bias, p0.y + bias, p1.x + bias, p1.y + bias);
        float4 v1 = make_float4(p2.x + bias, p2.y + bias, p3.x + bias, p3.y + bias);
        float* cp = C + ((size_t)t * GG + col) * BB + b0;
        *(float4*)cp       = v0;
        *(float4*)(cp + 4) = v1;
    }
}

// ---------------- fused 2-layer persistent LSTM recurrence ----------------
// Step s: layer0 @ t=s and layer1 @ t=s-1. One pass over h0 feeds BOTH Whh0 and Wih1.
// Gate phase: f32x2 partial reduction + fast MUFU activations.
__global__ void __launch_bounds__(256, 1) lstm_fused_kernel(
        const float* __restrict__ Whh0,
        const float* __restrict__ Wih1,
        const float* __restrict__ Whh1,
        const float* __restrict__ bih1,
        const float* __restrict__ bhh1) {
    extern __shared__ float smem[];
    float2* sWp0 = (float2*)smem;                 // [512 k][8 rp]  Whh0 (32 KB)
    float2* sWp1 = sWp0 + 512 * 8;                // [1024 k][8 rp] Wih1|Whh1 (64 KB)
    u64*    sPA  = (u64*)(sWp1 + 1024 * 8);       // [8 ks][8 rp][64 b] (32 KB)
    u64*    sPB  = sPA + 8 * 8 * 64;              // same (32 KB)
    float*  sC0  = (float*)(sPB + 8 * 8 * 64);    // [4][64]
    float*  sC1  = sC0 + 256;                     // [4][64]
    float*  sB1  = sC1 + 256;                     // [16]

    const int tid = threadIdx.x;
    const int cta = blockIdx.x;
    const int u0  = cta * 4;

    // ---- weight fills: sWp[k][rp] = (W[row_e][k], W[row_o][k]), rp = q*2+jh ----
    {
        const int rp = tid >> 5;              // 0..7
        const int ln = tid & 31;
        const int q = rp >> 1, jh = rp & 1;
        const int re = q * 512 + u0 + 2 * jh;
        const float* we0 = Whh0 + (size_t)re * 512;
        const float* wo0 = we0 + 512;
        const float* we1 = Wih1 + (size_t)re * 512;
        const float* wo1 = we1 + 512;
        const float* we2 = Whh1 + (size_t)re * 512;
        const float* wo2 = we2 + 512;
        #pragma unroll
        for (int i = 0; i < 4; ++i) {
            int k = ln * 16 + i * 4;
            float4 ae = *(const float4*)(we0 + k);
            float4 ao = *(const float4*)(wo0 + k);
            sWp0[(k + 0) * 8 + rp] = make_float2(ae.x, ao.x);
            sWp0[(k + 1) * 8 + rp] = make_float2(ae.y, ao.y);
            sWp0[(k + 2) * 8 + rp] = make_float2(ae.z, ao.z);
            sWp0[(k + 3) * 8 + rp] = make_float2(ae.w, ao.w);
            float4 be = *(const float4*)(we1 + k);
            float4 bo = *(const float4*)(wo1 + k);
            sWp1[(k + 0) * 8 + rp] = make_float2(be.x, bo.x);
            sWp1[(k + 1) * 8 + rp] = make_float2(be.y, bo.y);
            sWp1[(k + 2) * 8 + rp] = make_float2(be.z, bo.z);
            sWp1[(k + 3) * 8 + rp] = make_float2(be.w, bo.w);
            float4 ce = *(const float4*)(we2 + k);
            float4 co = *(const float4*)(wo2 + k);
            sWp1[(512 + k + 0) * 8 + rp] = make_float2(ce.x, co.x);
            sWp1[(512 + k + 1) * 8 + rp] = make_float2(ce.y, co.y);
            sWp1[(512 + k + 2) * 8 + rp] = make_float2(ce.z, co.z);
            sWp1[(512 + k + 3) * 8 + rp] = make_float2(ce.w, co.w);
        }
    }
    // ---- init ----
    {
        #pragma unroll
        for (int i = 0; i < 4; ++i) {
            int e   = tid + i * 256;
            int buf = e >> 9;
            int rem = e & 511;
            int r8  = rem >> 6;
            int b   = rem & 63;
            int grow = (r8 < 4) ? (u0 + r8) : (512 + u0 + (r8 - 4));
            g_hall[((size_t)buf * 1024 + grow) * 64 + b] = 0.f;
        }
        sC0[tid] = 0.f;
        sC1[tid] = 0.f;
        if (tid < 16) {
            int q = tid >> 2, j = tid & 3;
            int col = q * 512 + u0 + j;
            sB1[tid] = bih1[col] + bhh1[col];
        }
    }
    grid_sync();

    const int ks = tid >> 5;                // warp = k-slice
    const int bp = tid & 31;                // batch pair (batches 2bp, 2bp+1)
    const int jj = tid >> 6, bb = tid & 63; // gate-phase mapping

    int cur = 0;
    for (int s = 0; s <= TT; ++s) {
        const bool doA = (s < TT);
        const bool doB = (s >= 1);
        const int  sx  = doA ? s : (TT - 1);   // clamped (values unused when !doA)

        float xv[4];
        #pragma unroll
        for (int q = 0; q < 4; ++q)
            xv[q] = __ldg(g_xw + ((size_t)sx * GG + q * 512 + u0 + jj) * 64 + bb);

        // ---- pass 1 over h0[cur]: feeds accA (Whh0) and accB (Wih1) ----
        u64 aA0[8], aA1[8], aB0[8], aB1[8];
        #pragma unroll
        for (int i = 0; i < 8; ++i) { aA0[i] = 0ull; aA1[i] = 0ull; aB0[i] = 0ull; aB1[i] = 0ull; }
        {
            const u64* hp = (const u64*)(g_hall + ((size_t)cur * 1024 + ks * 64) * 64) + bp;
            const ulonglong2* wq0 = (const ulonglong2*)(sWp0 + (ks * 64) * 8);
            const ulonglong2* wq1 = (const ulonglong2*)(sWp1 + (ks * 64) * 8);
            #pragma unroll 8
            for (int kk = 0; kk < 64; ++kk) {
                u64 hraw = __ldcg(hp + (size_t)kk * 32);
                float2 hv = unpack2(hraw);
                u64 hd0 = pack2(hv.x, hv.x);
                u64 hd1 = pack2(hv.y, hv.y);
                const ulonglong2* wk0 = wq0 + kk * 4;
                const ulonglong2* wk1 = wq1 + kk * 4;
                #pragma unroll
                for (int p = 0; p < 4; ++p) {
                    ulonglong2 w2 = wk0[p];
                    ffma2(aA0[2 * p + 0], w2.x, hd0); ffma2(aA1[2 * p + 0], w2.x, hd1);
                    ffma2(aA0[2 * p + 1], w2.y, hd0); ffma2(aA1[2 * p + 1], w2.y, hd1);
                    ulonglong2 v2 = wk1[p];
                    ffma2(aB0[2 * p + 0], v2.x, hd0); ffma2(aB1[2 * p + 0], v2.x, hd1);
                    ffma2(aB0[2 * p + 1], v2.y, hd0); ffma2(aB1[2 * p + 1], v2.y, hd1);
                }
            }
        }
        // ---- pass 2 over h1[cur]: accB += Whh1 ----
        {
            const u64* hp = (const u64*)(g_hall + ((size_t)cur * 1024 + 512 + ks * 64) * 64) + bp;
            const ulonglong2* wq2 = (const ulonglong2*)(sWp1 + (512 + ks * 64) * 8);
            #pragma unroll 8
            for (int kk = 0; kk < 64; ++kk) {
                u64 hraw = __ldcg(hp + (size_t)kk * 32);
                float2 hv = unpack2(hraw);
                u64 hd0 = pack2(hv.x, hv.x);
                u64 hd1 = pack2(hv.y, hv.y);
                const ulonglong2* wk = wq2 + kk * 4;
                #pragma unroll
                for (int p = 0; p < 4; ++p) {
                    ulonglong2 w2 = wk[p];
                    ffma2(aB0[2 * p + 0], w2.x, hd0); ffma2(aB1[2 * p + 0], w2.x, hd1);
                    ffma2(aB0[2 * p + 1], w2.y, hd0); ffma2(aB1[2 * p + 1], w2.y, hd1);
                }
            }
        }
        #pragma unroll
        for (int rp = 0; rp < 8; ++rp) {
            *(ulonglong2*)(sPA + ((ks * 8 + rp) * 64 + 2 * bp)) = make_ulonglong2(aA0[rp], aA1[rp]);
            *(ulonglong2*)(sPB + ((ks * 8 + rp) * 64 + 2 * bp)) = make_ulonglong2(aB0[rp], aB1[rp]);
        }
        __syncthreads();

        // ---- gates A: layer0 @ t=s ----
        if (doA) {
            float g4[4];
            #pragma unroll
            for (int q = 0; q < 4; ++q) {
                int rp = q * 2 + (jj >> 1);
                int rh = jj & 1;
                u64 sum = sPA[(0 * 8 + rp) * 64 + bb];
                #pragma unroll
                for (int k2 = 1; k2 < 8; ++k2)
                    sum = fadd2(sum, sPA[(k2 * 8 + rp) * 64 + bb]);
                float2 sv = unpack2(sum);
                g4[q] = xv[q] + (rh ? sv.y : sv.x);
            }
            float iv = fast_sig(g4[0]);
            float fv = fast_sig(g4[1]);
            float gv = fast_tanh(g4[2]);
            float ov = fast_sig(g4[3]);
            float c = fv * sC0[jj * 64 + bb] + iv * gv;
            sC0[jj * 64 + bb] = c;
            float h = ov * fast_tanh(c);
            g_hall[((size_t)(cur ^ 1) * 1024 + u0 + jj) * 64 + bb] = h;
        }
        // ---- gates B: layer1 @ t=s-1 ----
        if (doB) {
            float g4[4];
            #pragma unroll
            for (int q = 0; q < 4; ++q) {
                int rp = q * 2 + (jj >> 1);
                int rh = jj & 1;
                u64 sum = sPB[(0 * 8 + rp) * 64 + bb];
                #pragma unroll
                for (int k2 = 1; k2 < 8; ++k2)
                    sum = fadd2(sum, sPB[(k2 * 8 + rp) * 64 + bb]);
                float2 sv = unpack2(sum);
                g4[q] = sB1[q * 4 + jj] + (rh ? sv.y : sv.x);
            }
            float iv = fast_sig(g4[0]);
            float fv = fast_sig(g4[1]);
            float gv = fast_tanh(g4[2]);
            float ov = fast_sig(g4[3]);
            float c = fv * sC1[jj * 64 + bb] + iv * gv;
            sC1[jj * 64 + bb] = c;
            float h = ov * fast_tanh(c);
            g_hall[((size_t)(cur ^ 1) * 1024 + 512 + u0 + jj) * 64 + bb] = h;
            g_y1[((size_t)(s - 1) * HH + u0 + jj) * 64 + bb] = h;
        }
        grid_sync();
        cur ^= 1;
    }
}

// ---------------- output gather ----------------
__global__ void out_kernel(const int* __restrict__ sen_len, float* __restrict__ out) {
    int idx = blockIdx.x * blockDim.x + threadIdx.x;
    if (idx >= BB * HH) return;
    int b = idx >> 9;
    int u = idx & (HH - 1);
    int t = sen_len[b] - 1;
    out[idx] = g_y1[((size_t)t * HH + u) * BB + b];
}

// ---------------- launch ----------------
static const int REC_SMEM = (512 * 8 + 1024 * 8) * 8   // sWp0 + sWp1 (float2)
                          + 2 * (8 * 8 * 64) * 8       // sPA + sPB (u64)
                          + 2 * 256 * 4 + 16 * 4;      // sC0,sC1,sB1  = 165952

extern "C" void kernel_launch(void* const* d_in, const int* in_sizes, int n_in,
                              void* d_out, int out_size) {
    const int*   src     = (const int*)d_in[0];
    const int*   sen_len = (const int*)d_in[1];
    const float* emb     = (const float*)d_in[2];
    const float* Wih0    = (const float*)d_in[3];
    const float* Whh0    = (const float*)d_in[4];
    const float* bih0    = (const float*)d_in[5];
    const float* bhh0    = (const float*)d_in[6];
    const float* Wih1    = (const float*)d_in[7];
    const float* Whh1    = (const float*)d_in[8];
    const float* bih1    = (const float*)d_in[9];
    const float* bhh1    = (const float*)d_in[10];
    float* out = (float*)d_out;

    cudaFuncSetAttribute(lstm_fused_kernel,
                         cudaFuncAttributeMaxDynamicSharedMemorySize, REC_SMEM);

    embed_kernel<<<(TT * EE * BB + 255) / 256, 256>>>(src, emb);

    dim3 ggrid(GG / 128, TT);
    gemm_xw_kernel<<<ggrid, 128>>>(Wih0, bih0, bhh0);

    lstm_fused_kernel<<<NCTA, 256, REC_SMEM>>>(Whh0, Wih1, Whh1, bih1, bhh1);

    out_kernel<<<(BB * HH + 255) / 256, 256>>>(sen_len, out);
}